// round 16
// baseline (speedup 1.0000x reference)
#include <cuda_runtime.h>
#include <cstdint>

// VectorQuantizer, tensor-core filtered, bit-exact rescore.
//   Phase 1 (approx): r~_k = bf16( fl(e2_k - 2 * s~_k) ), s~ via mma.sync tf32 m16n8k8.
//   Phase 2 (exact):  candidates = { k : r~_k <= min(r~) + W }; for each, the VALIDATED
//     bit-exact chain: s = fmaf-chain_d (ascending), dist = fl( fl(A+e2k) + fl(-2s) );
//     first-occurrence argmin via u64 key (bits(dist)<<32 | k), dist > 0.
//   Soundness: |r~ - (fl_dist - A)| <= tf32 err (2^-9 * Sum|x_d e_d| <= 2^-9*0.19)
//     + bf16 store err (<= 0.38*2^-9) + chain noise  ~= 1.5e-3;  W = 4.5e-3 > 2*delta.
//   A, e2 sequential mul-add chains and STE out = fl(x + fl(q-x)) as validated (rel_err 0).

#define NUM_CODES 512
#define DIMS      64
#define TPB       256
#define NPIX      (32 * 64 * 64)
#define IMG_STRIDE (64 * 4096)
#define TILE      64
#define NTILES    (NPIX / TILE)            // 2048
#define GRID      152
#define ESPAD     520                       // Es row stride (floats): bank-conflict-free
#define XSPAD     72                        // xs row stride (floats)
#define SLABPAD_U32 260                     // slab row stride in u32 (=520 bf16)
#define WINDOW    4.5e-3f

// smem layout (float units)
#define ES_OFF   0                          // Es[d][k]   64*520
#define E2_OFF   (DIMS * ESPAD)             // e2s[k]     512
#define XS_OFF   (E2_OFF + NUM_CODES)       // xs[d][px]  64*72
#define AS_OFF   (XS_OFF + DIMS * XSPAD)    // A[px]      64
#define WIN_OFF  (AS_OFF + TILE)            // win[px]    64
#define SLAB_OFF (WIN_OFF + TILE)           // slab       64*260 u32 (16B-aligned)
#define SMEM_FLOATS (SLAB_OFF + TILE * SLABPAD_U32)
#define SMEM_BYTES  (SMEM_FLOATS * 4)       // 220,672 bytes

typedef unsigned long long ull;

__device__ __forceinline__ void mma_tf32(float& c0, float& c1, float& c2, float& c3,
                                         uint32_t a0, uint32_t a1, uint32_t a2, uint32_t a3,
                                         uint32_t b0, uint32_t b1) {
    asm volatile(
        "mma.sync.aligned.m16n8k8.row.col.f32.tf32.tf32.f32 "
        "{%0,%1,%2,%3}, {%4,%5,%6,%7}, {%8,%9}, {%0,%1,%2,%3};"
        : "+f"(c0), "+f"(c1), "+f"(c2), "+f"(c3)
        : "r"(a0), "r"(a1), "r"(a2), "r"(a3), "r"(b0), "r"(b1));
}

__device__ __forceinline__ uint32_t pack_bf16x2(float lo, float hi) {
    uint32_t r;
    asm("cvt.rn.bf16x2.f32 %0, %1, %2;" : "=r"(r) : "f"(hi), "f"(lo));
    return r;
}

// Bit-exact dist for (px, k); compact (noinline: referenced from many branch sites).
__device__ __noinline__ ull exact_key(const float* __restrict__ xs,
                                      const float* __restrict__ Es,
                                      const float* __restrict__ e2s,
                                      const float* __restrict__ As,
                                      int px, int k) {
    float s = 0.0f;
    #pragma unroll 1
    for (int d = 0; d < DIMS; ++d)
        s = __fmaf_rn(xs[d * XSPAD + px], Es[d * ESPAD + k], s);
    const float dist = __fadd_rn(__fadd_rn(As[px], e2s[k]), __fmul_rn(-2.0f, s));
    return ((ull)__float_as_uint(dist) << 32) | (unsigned)k;
}

__global__ __launch_bounds__(TPB, 1)
void vq_kernel(const float* __restrict__ in,
               const float* __restrict__ emb,
               float* __restrict__ out) {
    extern __shared__ float smem[];
    float* Es  = smem + ES_OFF;
    float* e2s = smem + E2_OFF;
    float* xs  = smem + XS_OFF;
    float* As  = smem + AS_OFF;
    unsigned* win = reinterpret_cast<unsigned*>(smem + WIN_OFF);
    uint32_t* slab = reinterpret_cast<uint32_t*>(smem + SLAB_OFF);

    const int tid  = threadIdx.x;
    const int lane = tid & 31;
    const int w    = tid >> 5;
    const int g    = lane >> 2;     // mma group row 0..7
    const int t    = lane & 3;      // mma thread-in-group 0..3

    // ---- Stage codebook (transposed, padded) + sequential-chain squared norms ----
    #pragma unroll
    for (int kk = 0; kk < 2; ++kk) {
        const int k = tid + kk * TPB;
        const float4* row = reinterpret_cast<const float4*>(emb + k * DIMS);
        float s = 0.0f;
        #pragma unroll
        for (int j = 0; j < DIMS / 4; ++j) {
            float4 v = row[j];
            Es[(4 * j + 0) * ESPAD + k] = v.x;
            Es[(4 * j + 1) * ESPAD + k] = v.y;
            Es[(4 * j + 2) * ESPAD + k] = v.z;
            Es[(4 * j + 3) * ESPAD + k] = v.w;
            s = __fadd_rn(s, __fmul_rn(v.x, v.x));
            s = __fadd_rn(s, __fmul_rn(v.y, v.y));
            s = __fadd_rn(s, __fmul_rn(v.z, v.z));
            s = __fadd_rn(s, __fmul_rn(v.w, v.w));
        }
        e2s[k] = s;
    }
    __syncthreads();

    const int p0     = (w & 3) * 16;   // pixel block of this warp
    const int nbBase = (w >> 2) * 32;  // n-block range of this warp (32 blocks of 8 codes)

    for (int tile = blockIdx.x; tile < NTILES; tile += GRID) {
        const int tileBase = (tile >> 6) * IMG_STRIDE + (tile & 63) * TILE;

        // ---- Stage x tile [d][px], coalesced ----
        {
            const int i = tid & 63;
            const int h = tid >> 6;              // 0..3, 16 dims each
            const float* px = in + tileBase + i;
            #pragma unroll
            for (int j = 0; j < 16; ++j) {
                const int d = h * 16 + j;
                xs[d * XSPAD + i] = px[(size_t)d << 12];
            }
        }
        __syncthreads();

        // ---- A = ||x||^2 per pixel: strict sequential chain ascending d ----
        if (tid < TILE) {
            float A = 0.0f;
            #pragma unroll
            for (int d = 0; d < DIMS; ++d) {
                const float v = xs[d * XSPAD + tid];
                A = __fadd_rn(A, __fmul_rn(v, v));
            }
            As[tid] = A;
        }
        __syncthreads();

        // ---- Phase 1: mma tf32 approx. Warp: 16 px (p0..p0+15) x 256 codes ----
        // A-fragment preload: xr[r][c] = x[p0 + g + 8r][d = t + 4c]  (32 regs, reused 32x)
        uint32_t xr0[16], xr1[16];
        #pragma unroll
        for (int c = 0; c < 16; ++c) {
            const int d = t + 4 * c;
            xr0[c] = __float_as_uint(xs[d * XSPAD + p0 + g]);
            xr1[c] = __float_as_uint(xs[d * XSPAD + p0 + g + 8]);
        }

        #pragma unroll 2
        for (int j = 0; j < 32; ++j) {
            const int nb = nbBase + j;
            uint32_t b[16];
            #pragma unroll
            for (int s = 0; s < 8; ++s) {
                b[2 * s]     = __float_as_uint(Es[(8 * s + t)     * ESPAD + nb * 8 + g]);
                b[2 * s + 1] = __float_as_uint(Es[(8 * s + t + 4) * ESPAD + nb * 8 + g]);
            }
            float c0 = 0.0f, c1 = 0.0f, c2 = 0.0f, c3 = 0.0f;
            #pragma unroll
            for (int s = 0; s < 8; ++s)
                mma_tf32(c0, c1, c2, c3,
                         xr0[2 * s], xr1[2 * s], xr0[2 * s + 1], xr1[2 * s + 1],
                         b[2 * s], b[2 * s + 1]);

            // r~ = e2 - 2*s~ ; columns of C are k = nb*8 + 2t (+1); rows g, g+8
            const float2 e2p = *reinterpret_cast<const float2*>(e2s + nb * 8 + 2 * t);
            const float r0 = __fadd_rn(e2p.x, __fmul_rn(-2.0f, c0));
            const float r1 = __fadd_rn(e2p.y, __fmul_rn(-2.0f, c1));
            const float r2 = __fadd_rn(e2p.x, __fmul_rn(-2.0f, c2));
            const float r3 = __fadd_rn(e2p.y, __fmul_rn(-2.0f, c3));
            slab[(p0 + g)     * SLABPAD_U32 + nb * 4 + t] = pack_bf16x2(r0, r1);
            slab[(p0 + g + 8) * SLABPAD_U32 + nb * 4 + t] = pack_bf16x2(r2, r3);
        }
        __syncthreads();

        // ---- Phase 2: per-pixel scan + exact rescore. 4 threads per pixel. ----
        {
            const int px = tid >> 2;
            const int q  = tid & 3;
            const uint4* rowq = reinterpret_cast<const uint4*>(
                slab + px * SLABPAD_U32 + q * 64);

            // pass 1: min of this thread's 128 bf16 r-values
            float mn = 3.402823466e+38f;
            #pragma unroll
            for (int m = 0; m < 16; ++m) {
                const uint4 v = rowq[m];
                const uint32_t u[4] = {v.x, v.y, v.z, v.w};
                #pragma unroll
                for (int e = 0; e < 4; ++e) {
                    mn = fminf(mn, __uint_as_float(u[e] << 16));
                    mn = fminf(mn, __uint_as_float(u[e] & 0xFFFF0000u));
                }
            }
            mn = fminf(mn, __shfl_xor_sync(0xFFFFFFFFu, mn, 1));
            mn = fminf(mn, __shfl_xor_sync(0xFFFFFFFFu, mn, 2));
            const float thresh = mn + WINDOW;

            // pass 2: exact rescore of candidates
            ull bkey = 0xFFFFFFFFFFFFFFFFull;
            #pragma unroll 1
            for (int m = 0; m < 16; ++m) {
                const uint4 v = rowq[m];
                const uint32_t u[4] = {v.x, v.y, v.z, v.w};
                #pragma unroll
                for (int e = 0; e < 4; ++e) {
                    const int kb = q * 128 + m * 8 + 2 * e;
                    if (__uint_as_float(u[e] << 16) <= thresh) {
                        const ull kk = exact_key(xs, Es, e2s, As, px, kb);
                        bkey = bkey < kk ? bkey : kk;
                    }
                    if (__uint_as_float(u[e] & 0xFFFF0000u) <= thresh) {
                        const ull kk = exact_key(xs, Es, e2s, As, px, kb + 1);
                        bkey = bkey < kk ? bkey : kk;
                    }
                }
            }
            {
                const ull o1 = __shfl_xor_sync(0xFFFFFFFFu, bkey, 1);
                bkey = bkey < o1 ? bkey : o1;
                const ull o2 = __shfl_xor_sync(0xFFFFFFFFu, bkey, 2);
                bkey = bkey < o2 ? bkey : o2;
            }
            if (q == 0) win[px] = (unsigned)bkey;
        }
        __syncthreads();

        // ---- STE write: out = fl(x + fl(q - x)), coalesced ----
        {
            const int i = tid & 63;
            const int h = tid >> 6;
            const int k = (int)win[i];
            float* po = out + tileBase + i;
            #pragma unroll
            for (int j = 0; j < 16; ++j) {
                const int d = h * 16 + j;
                const float xv = xs[d * XSPAD + i];
                const float qv = Es[d * ESPAD + k];
                po[(size_t)d << 12] = __fadd_rn(xv, __fsub_rn(qv, xv));
            }
        }
        __syncthreads();   // protect xs/win/slab before next tile
    }
}

extern "C" void kernel_launch(void* const* d_in, const int* in_sizes, int n_in,
                              void* d_out, int out_size) {
    const float* in  = (const float*)d_in[0];   // inputs  [32,64,64,64] fp32
    const float* emb = (const float*)d_in[1];   // embedding [512,64] fp32
    float* out = (float*)d_out;

    cudaFuncSetAttribute(vq_kernel, cudaFuncAttributeMaxDynamicSharedMemorySize, SMEM_BYTES);
    vq_kernel<<<GRID, TPB, SMEM_BYTES>>>(in, emb, out);
}

// round 17
// speedup vs baseline: 2.7043x; 2.7043x over previous
#include <cuda_runtime.h>
#include <cstdint>

// VectorQuantizer, tensor-core filtered, bit-exact rescore (restructured phase 2).
//   Phase 1: s~ via mma.sync tf32 m16n8k8; r~ = fl(e2 - 2 s~); per-pixel fp32 min folded
//            in registers (quad shfl + atomicMin on float-ordered bits); r~ -> bf16 slab.
//   Phase 2a: scan slab, push candidates { k : bf16(r~) <= min + W } to smem list.
//   Phase 2b: batched parallel exact rescore (validated bit-exact chain), u64-key
//             atomicMin per pixel -> first-occurrence argmin (all exact ties included,
//             since any tied code satisfies the same window bound as the argmin).
//   W = 2e-3 >= 2.6 * (2*tf32_err + bf16_err) = 2.6 * 7.6e-4.
//   A, e2: sequential mul-add chains; STE out = fl(x + fl(q-x)). All validated rel_err=0.

#define NUM_CODES 512
#define DIMS      64
#define TPB       256
#define NPIX      (32 * 64 * 64)
#define IMG_STRIDE (64 * 4096)
#define TILE      64
#define NTILES    (NPIX / TILE)            // 2048
#define GRID      152
#define ESPAD     520
#define XSPAD     72
#define SLABPAD_U32 260
#define WINDOW    2.0e-3f
#define CAP       1024

// smem layout (float units)
#define ES_OFF   0                           // Es[d][k]    64*520
#define E2_OFF   (DIMS * ESPAD)              // e2s[k]      512
#define XS_OFF   (E2_OFF + NUM_CODES)        // xs[d][px]   64*72
#define AS_OFF   (XS_OFF + DIMS * XSPAD)     // A[px]       64
#define SLAB_OFF (AS_OFF + TILE)             // slab        64*260 u32
#define BK_OFF   (SLAB_OFF + TILE * SLABPAD_U32)  // bestkey  64 ull = 128 f
#define PM_OFF   (BK_OFF + TILE * 2)         // pxmin       64 u32
#define CL_OFF   (PM_OFF + TILE)             // candList    CAP u32
#define CNT_OFF  (CL_OFF + CAP)              // cnt         4 (padded)
#define SMEM_FLOATS (CNT_OFF + 4)
#define SMEM_BYTES  (SMEM_FLOATS * 4)        // ~225.5 KB

typedef unsigned long long ull;

__device__ __forceinline__ void mma_tf32(float& c0, float& c1, float& c2, float& c3,
                                         uint32_t a0, uint32_t a1, uint32_t a2, uint32_t a3,
                                         uint32_t b0, uint32_t b1) {
    asm volatile(
        "mma.sync.aligned.m16n8k8.row.col.f32.tf32.tf32.f32 "
        "{%0,%1,%2,%3}, {%4,%5,%6,%7}, {%8,%9}, {%0,%1,%2,%3};"
        : "+f"(c0), "+f"(c1), "+f"(c2), "+f"(c3)
        : "r"(a0), "r"(a1), "r"(a2), "r"(a3), "r"(b0), "r"(b1));
}

__device__ __forceinline__ uint32_t pack_bf16x2(float lo, float hi) {
    uint32_t r;
    asm("cvt.rn.bf16x2.f32 %0, %1, %2;" : "=r"(r) : "f"(hi), "f"(lo));
    return r;
}

__device__ __forceinline__ uint32_t ordbits(float f) {
    const uint32_t u = __float_as_uint(f);
    return (u & 0x80000000u) ? ~u : (u | 0x80000000u);
}
__device__ __forceinline__ float unordbits(uint32_t o) {
    const uint32_t u = (o & 0x80000000u) ? (o ^ 0x80000000u) : ~o;
    return __uint_as_float(u);
}

// Bit-exact dist key for (px, k). Fully inlined/unrolled: loads pipeline ahead of chain.
__device__ __forceinline__ ull exact_key(const float* __restrict__ xs,
                                         const float* __restrict__ Es,
                                         const float* __restrict__ e2s,
                                         const float* __restrict__ As,
                                         int px, int k) {
    float s = 0.0f;
    #pragma unroll
    for (int d = 0; d < DIMS; ++d)
        s = __fmaf_rn(xs[d * XSPAD + px], Es[d * ESPAD + k], s);
    const float dist = __fadd_rn(__fadd_rn(As[px], e2s[k]), __fmul_rn(-2.0f, s));
    return ((ull)__float_as_uint(dist) << 32) | (unsigned)k;
}

__global__ __launch_bounds__(TPB, 1)
void vq_kernel(const float* __restrict__ in,
               const float* __restrict__ emb,
               float* __restrict__ out) {
    extern __shared__ float smem[];
    float* Es  = smem + ES_OFF;
    float* e2s = smem + E2_OFF;
    float* xs  = smem + XS_OFF;
    float* As  = smem + AS_OFF;
    uint32_t* slab   = reinterpret_cast<uint32_t*>(smem + SLAB_OFF);
    ull*      bkey   = reinterpret_cast<ull*>(smem + BK_OFF);
    uint32_t* pxmin  = reinterpret_cast<uint32_t*>(smem + PM_OFF);
    uint32_t* cand   = reinterpret_cast<uint32_t*>(smem + CL_OFF);
    int*      cnt    = reinterpret_cast<int*>(smem + CNT_OFF);

    const int tid  = threadIdx.x;
    const int lane = tid & 31;
    const int w    = tid >> 5;
    const int g    = lane >> 2;     // mma group row 0..7
    const int t    = lane & 3;      // mma thread-in-group 0..3

    // ---- Stage codebook (transposed, padded) + sequential-chain squared norms ----
    #pragma unroll
    for (int kk = 0; kk < 2; ++kk) {
        const int k = tid + kk * TPB;
        const float4* row = reinterpret_cast<const float4*>(emb + k * DIMS);
        float s = 0.0f;
        #pragma unroll
        for (int j = 0; j < DIMS / 4; ++j) {
            float4 v = row[j];
            Es[(4 * j + 0) * ESPAD + k] = v.x;
            Es[(4 * j + 1) * ESPAD + k] = v.y;
            Es[(4 * j + 2) * ESPAD + k] = v.z;
            Es[(4 * j + 3) * ESPAD + k] = v.w;
            s = __fadd_rn(s, __fmul_rn(v.x, v.x));
            s = __fadd_rn(s, __fmul_rn(v.y, v.y));
            s = __fadd_rn(s, __fmul_rn(v.z, v.z));
            s = __fadd_rn(s, __fmul_rn(v.w, v.w));
        }
        e2s[k] = s;
    }
    __syncthreads();

    const int p0     = (w & 3) * 16;
    const int nbBase = (w >> 2) * 32;

    for (int tile = blockIdx.x; tile < NTILES; tile += GRID) {
        const int tileBase = (tile >> 6) * IMG_STRIDE + (tile & 63) * TILE;

        // ---- Stage x tile [d][px], coalesced ----
        {
            const int i = tid & 63;
            const int h = tid >> 6;
            const float* px = in + tileBase + i;
            #pragma unroll
            for (int j = 0; j < 16; ++j) {
                const int d = h * 16 + j;
                xs[d * XSPAD + i] = px[(size_t)d << 12];
            }
        }
        __syncthreads();

        // ---- A per pixel (strict sequential chain) + per-tile state init ----
        if (tid < TILE) {
            float A = 0.0f;
            #pragma unroll
            for (int d = 0; d < DIMS; ++d) {
                const float v = xs[d * XSPAD + tid];
                A = __fadd_rn(A, __fmul_rn(v, v));
            }
            As[tid] = A;
            bkey[tid]  = 0xFFFFFFFFFFFFFFFFull;
            pxmin[tid] = 0xFFFFFFFFu;
        }
        if (tid == 0) *cnt = 0;
        __syncthreads();

        // ---- Phase 1: mma tf32, register min fold, bf16 slab store ----
        uint32_t xr0[16], xr1[16];
        #pragma unroll
        for (int c = 0; c < 16; ++c) {
            const int d = t + 4 * c;
            xr0[c] = __float_as_uint(xs[d * XSPAD + p0 + g]);
            xr1[c] = __float_as_uint(xs[d * XSPAD + p0 + g + 8]);
        }

        float mnA = 3.402823466e+38f, mnB = 3.402823466e+38f;

        #pragma unroll 2
        for (int j = 0; j < 32; ++j) {
            const int nb = nbBase + j;
            uint32_t b[16];
            #pragma unroll
            for (int s = 0; s < 8; ++s) {
                b[2 * s]     = __float_as_uint(Es[(8 * s + t)     * ESPAD + nb * 8 + g]);
                b[2 * s + 1] = __float_as_uint(Es[(8 * s + t + 4) * ESPAD + nb * 8 + g]);
            }
            float c0 = 0.0f, c1 = 0.0f, c2 = 0.0f, c3 = 0.0f;
            #pragma unroll
            for (int s = 0; s < 8; ++s)
                mma_tf32(c0, c1, c2, c3,
                         xr0[2 * s], xr1[2 * s], xr0[2 * s + 1], xr1[2 * s + 1],
                         b[2 * s], b[2 * s + 1]);

            const float2 e2p = *reinterpret_cast<const float2*>(e2s + nb * 8 + 2 * t);
            const float r0 = __fadd_rn(e2p.x, __fmul_rn(-2.0f, c0));
            const float r1 = __fadd_rn(e2p.y, __fmul_rn(-2.0f, c1));
            const float r2 = __fadd_rn(e2p.x, __fmul_rn(-2.0f, c2));
            const float r3 = __fadd_rn(e2p.y, __fmul_rn(-2.0f, c3));
            mnA = fminf(mnA, fminf(r0, r1));
            mnB = fminf(mnB, fminf(r2, r3));
            slab[(p0 + g)     * SLABPAD_U32 + nb * 4 + t] = pack_bf16x2(r0, r1);
            slab[(p0 + g + 8) * SLABPAD_U32 + nb * 4 + t] = pack_bf16x2(r2, r3);
        }

        // quad reduce (lanes 4g..4g+3 share pixel rows g / g+8)
        mnA = fminf(mnA, __shfl_xor_sync(0xFFFFFFFFu, mnA, 1));
        mnA = fminf(mnA, __shfl_xor_sync(0xFFFFFFFFu, mnA, 2));
        mnB = fminf(mnB, __shfl_xor_sync(0xFFFFFFFFu, mnB, 1));
        mnB = fminf(mnB, __shfl_xor_sync(0xFFFFFFFFu, mnB, 2));
        if (t == 0) {
            atomicMin(&pxmin[p0 + g],     ordbits(mnA));
            atomicMin(&pxmin[p0 + g + 8], ordbits(mnB));
        }
        __syncthreads();

        // ---- Phase 2a: scan slab, push candidates ----
        {
            const int px = tid >> 2;
            const int q  = tid & 3;
            const float thresh = unordbits(pxmin[px]) + WINDOW;
            const uint4* rowq = reinterpret_cast<const uint4*>(
                slab + px * SLABPAD_U32 + q * 64);

            #pragma unroll
            for (int m = 0; m < 16; ++m) {
                const uint4 v = rowq[m];
                const uint32_t u[4] = {v.x, v.y, v.z, v.w};
                #pragma unroll
                for (int e = 0; e < 4; ++e) {
                    const int kb = q * 128 + m * 8 + 2 * e;
                    if (__uint_as_float(u[e] << 16) <= thresh) {
                        const int pos = atomicAdd(cnt, 1);
                        if (pos < CAP) cand[pos] = ((unsigned)px << 16) | (unsigned)kb;
                        else atomicMin(&bkey[px], exact_key(xs, Es, e2s, As, px, kb));
                    }
                    if (__uint_as_float(u[e] & 0xFFFF0000u) <= thresh) {
                        const int pos = atomicAdd(cnt, 1);
                        if (pos < CAP) cand[pos] = ((unsigned)px << 16) | (unsigned)(kb + 1);
                        else atomicMin(&bkey[px], exact_key(xs, Es, e2s, As, px, kb + 1));
                    }
                }
            }
        }
        __syncthreads();

        // ---- Phase 2b: batched parallel exact rescore ----
        {
            const int n = min(*cnt, CAP);
            for (int i = tid; i < n; i += TPB) {
                const uint32_t c = cand[i];
                const int px = (int)(c >> 16);
                const int k  = (int)(c & 0xFFFFu);
                atomicMin(&bkey[px], exact_key(xs, Es, e2s, As, px, k));
            }
        }
        __syncthreads();

        // ---- STE write: out = fl(x + fl(q - x)), coalesced ----
        {
            const int i = tid & 63;
            const int h = tid >> 6;
            const int k = (int)(unsigned)bkey[i];   // low 32 bits = winning k
            float* po = out + tileBase + i;
            #pragma unroll
            for (int j = 0; j < 16; ++j) {
                const int d = h * 16 + j;
                const float xv = xs[d * XSPAD + i];
                const float qv = Es[d * ESPAD + k];
                po[(size_t)d << 12] = __fadd_rn(xv, __fsub_rn(qv, xv));
            }
        }
        __syncthreads();
    }
}

extern "C" void kernel_launch(void* const* d_in, const int* in_sizes, int n_in,
                              void* d_out, int out_size) {
    const float* in  = (const float*)d_in[0];   // inputs  [32,64,64,64] fp32
    const float* emb = (const float*)d_in[1];   // embedding [512,64] fp32
    float* out = (float*)d_out;

    cudaFuncSetAttribute(vq_kernel, cudaFuncAttributeMaxDynamicSharedMemorySize, SMEM_BYTES);
    vq_kernel<<<GRID, TPB, SMEM_BYTES>>>(in, emb, out);
}